// round 13
// baseline (speedup 1.0000x reference)
#include <cuda_runtime.h>
#include <cuda_bf16.h>
#include <cuda_pipeline.h>

// Problem constants (constexpr, not macros)
constexpr int CB  = 2;     // batch
constexpr int CL  = 128;   // seq len
constexpr int CD  = 256;   // model dim
constexpr int CH  = 8;     // heads
constexpr int CDK = 32;    // head dim
constexpr float C_EPS = 1e-6f;
constexpr float C_INV_TEMP = 0.17677669529663687f;   // 1/sqrt(32)

// Scratch (allocation-free rule: __device__ globals)
__device__ float g_pv[CB * CL * CD];
__device__ float g_dotqk[CB * CH * CL];
__device__ float g_outhead[CB * CL * CD];

extern __shared__ float sm_dyn[];

// ---------------------------------------------------------------------------
// K1: projection kernel.  grid=(8,8,2), block=512, dynamic smem 136KB.
//  z=0: fused Q&K projection for head bx, rows [m0,m0+32): pq,pk tiles in
//       registers (2r x 2c microtile, split-K x2), LN fused on q; writes
//       ONLY dot_qk[b,h,j].
//  z=1: V projection 32x32 tile -> g_pv (same micro-structure).
// Layout (floats): Aq4 f4[2048] @0 (32KB) | Ak4 @8192 | Bq[8192] @16384 |
//                  Bk @24576 | red[2048] @32768 (8KB)
// ---------------------------------------------------------------------------
__global__ __launch_bounds__(512)
void ct_proj_kernel(const float* __restrict__ qin,
                    const float* __restrict__ kin,
                    const float* __restrict__ vin,
                    const float* __restrict__ Wq,
                    const float* __restrict__ Wk,
                    const float* __restrict__ Wv,
                    const float* __restrict__ ln_g,
                    const float* __restrict__ ln_b) {
    const int bz = blockIdx.z;
    int tid = threadIdx.x;
    int m0 = blockIdx.y * 32;
    int n0 = blockIdx.x * 32;          // z=0: head*32 within H*DK; z=1: col tile

    float4* Aq4 = (float4*)sm_dyn;             // [kk(64)][row(32)]
    float4* Ak4 = (float4*)(sm_dyn + 8192);
    float*  Bq  = sm_dyn + 16384;              // [k(256)][col(32)]
    float*  Bk  = sm_dyn + 24576;
    float*  red = sm_dyn + 32768;              // [8][256]

    // microtile coords
    int g   = tid >> 8;                 // split-K half
    int idx = tid & 255;
    int rg  = idx >> 4;                 // row group 0..15 -> rows 2rg,2rg+1
    int cpp = idx & 15;                 // col pair 0..15 -> cols 2cpp,2cpp+1
    int r0 = rg * 2, r1 = r0 + 1, c0 = cpp * 2;
    int kbase = g * 32;                 // kk4 range per half

    if (bz == 0) {
        // ---- issue all async copies (q,k,Wq,Wk) ------------------------
        {
            int r = tid & 31, k4b = tid >> 5;       // k4b 0..15
#pragma unroll
            for (int it = 0; it < 4; it++) {
                int kk = k4b + it * 16;             // 0..63
                __pipeline_memcpy_async(&Aq4[kk * 32 + r], &qin[(m0 + r) * CD + kk * 4], 16);
                __pipeline_memcpy_async(&Ak4[kk * 32 + r], &kin[(m0 + r) * CD + kk * 4], 16);
            }
            int c4 = tid & 7, kb = tid >> 3;        // kb 0..63
#pragma unroll
            for (int it = 0; it < 4; it++) {
                int k = kb + it * 64;               // 0..255
                __pipeline_memcpy_async(&Bq[k * 32 + c4 * 4], &Wq[k * CD + n0 + c4 * 4], 16);
                __pipeline_memcpy_async(&Bk[k * 32 + c4 * 4], &Wk[k * CD + n0 + c4 * 4], 16);
            }
        }
        __pipeline_commit();

        // ---- LN stats from global while copies fly (warp w: rows w,w+16)
        int w = tid >> 5, lane = tid & 31;
        float mu_a, rs_a, mu_b, rs_b;
#pragma unroll
        for (int half = 0; half < 2; half++) {
            int rr = w + half * 16;
            const float* rowp = qin + (m0 + rr) * CD;
            float s1 = 0.f, s2 = 0.f;
#pragma unroll
            for (int e = 0; e < 8; e++) {
                float x = rowp[lane + 32 * e];
                s1 += x; s2 += x * x;
            }
#pragma unroll
            for (int o = 16; o > 0; o >>= 1) {
                s1 += __shfl_xor_sync(0xFFFFFFFFu, s1, o);
                s2 += __shfl_xor_sync(0xFFFFFFFFu, s2, o);
            }
            float mu  = s1 * (1.0f / 256.0f);
            float var = s2 * (1.0f / 256.0f) - mu * mu;
            float rs  = rsqrtf(var + C_EPS);
            if (half == 0) { mu_a = mu; rs_a = rs; }
            else           { mu_b = mu; rs_b = rs; }
        }

        __pipeline_wait_prior(0);
        __syncthreads();

        // ---- in-smem LN transform of Aq (warp w owns rows w, w+16) -----
#pragma unroll
        for (int half = 0; half < 2; half++) {
            int rr = w + half * 16;
            float mu = half ? mu_b : mu_a;
            float rs = half ? rs_b : rs_a;
#pragma unroll
            for (int c = 0; c < 2; c++) {
                int kk = lane + c * 32;
                float4 p  = Aq4[kk * 32 + rr];
                float4 g4 = ((const float4*)ln_g)[kk];
                float4 b4 = ((const float4*)ln_b)[kk];
                p.x = (p.x - mu) * rs * g4.x + b4.x;
                p.y = (p.y - mu) * rs * g4.y + b4.y;
                p.z = (p.z - mu) * rs * g4.z + b4.z;
                p.w = (p.w - mu) * rs * g4.w + b4.w;
                Aq4[kk * 32 + rr] = p;
            }
        }
        __syncthreads();

        // ---- compute: 2r x 2c for both q and k over this K-half --------
        float q00 = 0.f, q01 = 0.f, q10 = 0.f, q11 = 0.f;
        float k00 = 0.f, k01 = 0.f, k10 = 0.f, k11 = 0.f;
#pragma unroll 8
        for (int kk = 0; kk < 32; kk++) {
            int kk4 = kbase + kk;
            float4 aq_0 = Aq4[kk4 * 32 + r0];
            float4 aq_1 = Aq4[kk4 * 32 + r1];
            float4 ak_0 = Ak4[kk4 * 32 + r0];
            float4 ak_1 = Ak4[kk4 * 32 + r1];
            const float* bq = &Bq[(kk4 * 4) * 32 + c0];
            const float* bk = &Bk[(kk4 * 4) * 32 + c0];
            float2 bq0 = *(const float2*)&bq[0 * 32];
            float2 bq1 = *(const float2*)&bq[1 * 32];
            float2 bq2 = *(const float2*)&bq[2 * 32];
            float2 bq3 = *(const float2*)&bq[3 * 32];
            q00 += aq_0.x * bq0.x; q01 += aq_0.x * bq0.y;
            q10 += aq_1.x * bq0.x; q11 += aq_1.x * bq0.y;
            q00 += aq_0.y * bq1.x; q01 += aq_0.y * bq1.y;
            q10 += aq_1.y * bq1.x; q11 += aq_1.y * bq1.y;
            q00 += aq_0.z * bq2.x; q01 += aq_0.z * bq2.y;
            q10 += aq_1.z * bq2.x; q11 += aq_1.z * bq2.y;
            q00 += aq_0.w * bq3.x; q01 += aq_0.w * bq3.y;
            q10 += aq_1.w * bq3.x; q11 += aq_1.w * bq3.y;
            float2 bk0 = *(const float2*)&bk[0 * 32];
            float2 bk1 = *(const float2*)&bk[1 * 32];
            float2 bk2 = *(const float2*)&bk[2 * 32];
            float2 bk3 = *(const float2*)&bk[3 * 32];
            k00 += ak_0.x * bk0.x; k01 += ak_0.x * bk0.y;
            k10 += ak_1.x * bk0.x; k11 += ak_1.x * bk0.y;
            k00 += ak_0.y * bk1.x; k01 += ak_0.y * bk1.y;
            k10 += ak_1.y * bk1.x; k11 += ak_1.y * bk1.y;
            k00 += ak_0.z * bk2.x; k01 += ak_0.z * bk2.y;
            k10 += ak_1.z * bk2.x; k11 += ak_1.z * bk2.y;
            k00 += ak_0.w * bk3.x; k01 += ak_0.w * bk3.y;
            k10 += ak_1.w * bk3.x; k11 += ak_1.w * bk3.y;
        }

        // ---- combine split-K halves ------------------------------------
        if (g == 1) {
            red[0 * 256 + idx] = q00; red[1 * 256 + idx] = q01;
            red[2 * 256 + idx] = q10; red[3 * 256 + idx] = q11;
            red[4 * 256 + idx] = k00; red[5 * 256 + idx] = k01;
            red[6 * 256 + idx] = k10; red[7 * 256 + idx] = k11;
        }
        __syncthreads();
        if (g == 0) {
            q00 += red[0 * 256 + idx]; q01 += red[1 * 256 + idx];
            q10 += red[2 * 256 + idx]; q11 += red[3 * 256 + idx];
            k00 += red[4 * 256 + idx]; k01 += red[5 * 256 + idx];
            k10 += red[6 * 256 + idx]; k11 += red[7 * 256 + idx];

            // ---- dot over the 32-col head dim (16-lane butterfly) ------
            float d0 = q00 * k00 + q01 * k01;
            float d1 = q10 * k10 + q11 * k11;
#pragma unroll
            for (int o = 1; o < 16; o <<= 1) {
                d0 += __shfl_xor_sync(0xFFFFFFFFu, d0, o);
                d1 += __shfl_xor_sync(0xFFFFFFFFu, d1, o);
            }
            if (cpp == 0) {
                int m = m0 + r0;
                g_dotqk[(m >> 7) * (CH * CL) + blockIdx.x * CL + (m & 127)] = d0;
                m = m0 + r1;
                g_dotqk[(m >> 7) * (CH * CL) + blockIdx.x * CL + (m & 127)] = d1;
            }
        }
    } else {
        // ---- V projection: 32x32 tile, 2r x 2c, split-K x2 -------------
        {
            int r = tid & 31, k4b = tid >> 5;
#pragma unroll
            for (int it = 0; it < 4; it++) {
                int kk = k4b + it * 16;
                __pipeline_memcpy_async(&Aq4[kk * 32 + r], &vin[(m0 + r) * CD + kk * 4], 16);
            }
            int c4 = tid & 7, kb = tid >> 3;
#pragma unroll
            for (int it = 0; it < 4; it++) {
                int k = kb + it * 64;
                __pipeline_memcpy_async(&Bq[k * 32 + c4 * 4], &Wv[k * CD + n0 + c4 * 4], 16);
            }
        }
        __pipeline_commit();
        __pipeline_wait_prior(0);
        __syncthreads();

        float v00 = 0.f, v01 = 0.f, v10 = 0.f, v11 = 0.f;
#pragma unroll 8
        for (int kk = 0; kk < 32; kk++) {
            int kk4 = kbase + kk;
            float4 a_0 = Aq4[kk4 * 32 + r0];
            float4 a_1 = Aq4[kk4 * 32 + r1];
            const float* bv = &Bq[(kk4 * 4) * 32 + c0];
            float2 b0 = *(const float2*)&bv[0 * 32];
            float2 b1 = *(const float2*)&bv[1 * 32];
            float2 b2 = *(const float2*)&bv[2 * 32];
            float2 b3 = *(const float2*)&bv[3 * 32];
            v00 += a_0.x * b0.x; v01 += a_0.x * b0.y;
            v10 += a_1.x * b0.x; v11 += a_1.x * b0.y;
            v00 += a_0.y * b1.x; v01 += a_0.y * b1.y;
            v10 += a_1.y * b1.x; v11 += a_1.y * b1.y;
            v00 += a_0.z * b2.x; v01 += a_0.z * b2.y;
            v10 += a_1.z * b2.x; v11 += a_1.z * b2.y;
            v00 += a_0.w * b3.x; v01 += a_0.w * b3.y;
            v10 += a_1.w * b3.x; v11 += a_1.w * b3.y;
        }

        if (g == 1) {
            red[0 * 256 + idx] = v00; red[1 * 256 + idx] = v01;
            red[2 * 256 + idx] = v10; red[3 * 256 + idx] = v11;
        }
        __syncthreads();
        if (g == 0) {
            v00 += red[0 * 256 + idx]; v01 += red[1 * 256 + idx];
            v10 += red[2 * 256 + idx]; v11 += red[3 * 256 + idx];
            *(float2*)&g_pv[(m0 + r0) * CD + n0 + c0] = make_float2(v00, v01);
            *(float2*)&g_pv[(m0 + r1) * CD + n0 + c0] = make_float2(v10, v11);
        }
    }
}

// ---------------------------------------------------------------------------
// K2: fused attention per (b,i).  Prologue computes time-kernel tables
// (chi, lb) in smem; warp h owns head h: shuffle-only softmax, attn write,
// V-reduction.  grid=256 (b*128+i), block=256, static smem.
// ---------------------------------------------------------------------------
__global__ __launch_bounds__(256)
void ct_attn_kernel(const float* __restrict__ t,
                    const float* __restrict__ omega,
                    const float* __restrict__ s,
                    float* __restrict__ attn_out) {
    int bid = blockIdx.x;
    int b = bid >> 7;
    int i = bid & 127;
    int tid = threadIdx.x;
    int h = tid >> 5;
    int lane = tid & 31;
    int j0 = lane * 4;

    __shared__ float sh_lb[128];        // omega * INV_TEMP * psi
    __shared__ float sh_chi[128];       // sum_r exp(-dt*s_r)
    __shared__ float sh_ws[8][128];

    if (tid < 128) {
        int j = tid;
        float s0 = s[0], s1 = s[1], s2 = s[2], s3 = s[3];
        float dt = fabsf(t[b * CL + i] - t[b * CL + j]);
        float c0 = __expf(-dt * s0), c1 = __expf(-dt * s1);
        float c2 = __expf(-dt * s2), c3 = __expf(-dt * s3);
        sh_chi[j] = (c0 + c1) + (c2 + c3);
        float psi = (c0 * c0 + c1 * c1) + (c2 * c2 + c3 * c3);
        sh_lb[j] = omega[(b * CL + i) * CL + j] * C_INV_TEMP * psi;
    }
    __syncthreads();

    float4 dq = *(const float4*)&g_dotqk[b * (CH * CL) + h * CL + j0];
    float4 lb = *(const float4*)&sh_lb[j0];
    float4 ch = *(const float4*)&sh_chi[j0];

    float l0 = (j0 + 0 <= i) ? lb.x * dq.x : -1e9f;
    float l1 = (j0 + 1 <= i) ? lb.y * dq.y : -1e9f;
    float l2 = (j0 + 2 <= i) ? lb.z * dq.z : -1e9f;
    float l3 = (j0 + 3 <= i) ? lb.w * dq.w : -1e9f;

    float m = fmaxf(fmaxf(l0, l1), fmaxf(l2, l3));
#pragma unroll
    for (int o = 16; o > 0; o >>= 1)
        m = fmaxf(m, __shfl_xor_sync(0xFFFFFFFFu, m, o));

    float e0 = __expf(l0 - m), e1 = __expf(l1 - m);
    float e2 = __expf(l2 - m), e3 = __expf(l3 - m);
    float su = (e0 + e1) + (e2 + e3);
#pragma unroll
    for (int o = 16; o > 0; o >>= 1)
        su += __shfl_xor_sync(0xFFFFFFFFu, su, o);

    float inv = 1.0f / su;
    float4 a4 = make_float4(e0 * inv, e1 * inv, e2 * inv, e3 * inv);
    *(float4*)&attn_out[((b * CH + h) * CL + i) * CL + j0] = a4;

    float4 w4 = make_float4(a4.x * ch.x, a4.y * ch.y, a4.z * ch.z, a4.w * ch.w);
    *(float4*)&sh_ws[h][j0] = w4;
    __syncwarp();

    // V reduction: outhead[b,i,h,d] = sum_j ws[h][j] * pv[b,j,h,d]
    const float* pvp = g_pv + b * CL * CD + h * CDK + lane;
    const float* wsp = sh_ws[h];
    float a0 = 0.f, a1 = 0.f, a2 = 0.f, a3 = 0.f;
#pragma unroll 8
    for (int j = 0; j < 128; j += 4) {
        a0 += wsp[j + 0] * pvp[(j + 0) * CD];
        a1 += wsp[j + 1] * pvp[(j + 1) * CD];
        a2 += wsp[j + 2] * pvp[(j + 2) * CD];
        a3 += wsp[j + 3] * pvp[(j + 3) * CD];
    }
    g_outhead[bid * CD + h * CDK + lane] = (a0 + a1) + (a2 + a3);
}

// ---------------------------------------------------------------------------
// K3: out = outhead @ fc_w + fc_b + q (residual).
// grid=(8,16), block=512: split-K x2 (each half does K=128), smem combine.
// Dynamic smem 50KB: A4 f4[1024] @0 | Bs[8192] @16KB | red[512] @48KB.
// ---------------------------------------------------------------------------
__global__ __launch_bounds__(512)
void ct_final_kernel(const float* __restrict__ W,
                     const float* __restrict__ bias,
                     const float* __restrict__ resid,
                     float* __restrict__ out) {
    float4* A4  = (float4*)sm_dyn;
    float*  Bs  = sm_dyn + 4096;
    float*  red = sm_dyn + 4096 + 8192;

    int tid = threadIdx.x;
    int m0 = blockIdx.y * 16, n0 = blockIdx.x * 32;

    {
        int r = tid & 15, kk4g = tid >> 4;       // 0..31
#pragma unroll
        for (int it = 0; it < 2; it++) {
            int kk = kk4g + it * 32;
            __pipeline_memcpy_async(&A4[kk * 16 + r],
                                    &g_outhead[(m0 + r) * CD + kk * 4], 16);
        }
        int c4 = tid & 7, k0 = tid >> 3;         // 0..63
#pragma unroll
        for (int it = 0; it < 4; it++) {
            int kx = k0 + it * 64;
            __pipeline_memcpy_async(&Bs[kx * 32 + c4 * 4],
                                    &W[kx * CD + n0 + c4 * 4], 16);
        }
    }
    __pipeline_commit();
    __pipeline_wait_prior(0);
    __syncthreads();

    int g   = tid >> 8;                  // split-K half
    int idx = tid & 255;
    int lr  = idx >> 4;
    int lc2 = (idx & 15) * 2;
    float acc0 = 0.f, acc1 = 0.f;
    int base = g * 32;

#pragma unroll 16
    for (int kk = 0; kk < 32; kk++) {
        int kk4 = base + kk;
        float4 a4 = A4[kk4 * 16 + lr];
        const float* brow = &Bs[(kk4 * 4) * 32 + lc2];
        float2 b0 = *(const float2*)&brow[0 * 32];
        float2 b1 = *(const float2*)&brow[1 * 32];
        float2 b2 = *(const float2*)&brow[2 * 32];
        float2 b3 = *(const float2*)&brow[3 * 32];
        acc0 += a4.x * b0.x; acc1 += a4.x * b0.y;
        acc0 += a4.y * b1.x; acc1 += a4.y * b1.y;
        acc0 += a4.z * b2.x; acc1 += a4.z * b2.y;
        acc0 += a4.w * b3.x; acc1 += a4.w * b3.y;
    }

    if (g == 1) {
        red[idx * 2 + 0] = acc0;
        red[idx * 2 + 1] = acc1;
    }
    __syncthreads();
    if (g == 0) {
        acc0 += red[idx * 2 + 0];
        acc1 += red[idx * 2 + 1];
        int row = m0 + lr, col = n0 + lc2;
        float2 bi = *(const float2*)&bias[col];
        float2 re = *(const float2*)&resid[row * CD + col];
        *(float2*)&out[row * CD + col] =
            make_float2(acc0 + bi.x + re.x, acc1 + bi.y + re.y);
    }
}

// ---------------------------------------------------------------------------
// Launch.  Inputs: q,k,v,t,omega,mask,Wq,Wk,Wv,s,fc_w,fc_b,ln_g,ln_b
// Output: out (65536 f32) then attn (262144 f32)
// ---------------------------------------------------------------------------
extern "C" void kernel_launch(void* const* d_in, const int* in_sizes, int n_in,
                              void* d_out, int out_size) {
    const float* q     = (const float*)d_in[0];
    const float* k     = (const float*)d_in[1];
    const float* v     = (const float*)d_in[2];
    const float* t     = (const float*)d_in[3];
    const float* omega = (const float*)d_in[4];
    // d_in[5] = mask (causal triu) -- applied analytically
    const float* Wq    = (const float*)d_in[6];
    const float* Wk    = (const float*)d_in[7];
    const float* Wv    = (const float*)d_in[8];
    const float* s     = (const float*)d_in[9];
    const float* fc_w  = (const float*)d_in[10];
    const float* fc_b  = (const float*)d_in[11];
    const float* ln_g  = (const float*)d_in[12];
    const float* ln_b  = (const float*)d_in[13];

    float* out      = (float*)d_out;
    float* attn_out = out + CB * CL * CD;

    // Opt in to >48KB dynamic smem (capture-safe host calls)
    cudaFuncSetAttribute(ct_proj_kernel,
                         cudaFuncAttributeMaxDynamicSharedMemorySize, 140 * 1024);
    cudaFuncSetAttribute(ct_final_kernel,
                         cudaFuncAttributeMaxDynamicSharedMemorySize, 50 * 1024);

    ct_proj_kernel<<<dim3(8, 8, 2), 512, 140 * 1024>>>(q, k, v, Wq, Wk, Wv, ln_g, ln_b);
    ct_attn_kernel<<<CB * CL, 256>>>(t, omega, s, attn_out);
    ct_final_kernel<<<dim3(8, 16), 512, 50 * 1024>>>(fc_w, fc_b, q, out);
}

// round 15
// speedup vs baseline: 1.0012x; 1.0012x over previous
#include <cuda_runtime.h>
#include <cuda_bf16.h>
#include <cuda_pipeline.h>

// Problem constants (constexpr, not macros)
constexpr int CB  = 2;     // batch
constexpr int CL  = 128;   // seq len
constexpr int CD  = 256;   // model dim
constexpr int CH  = 8;     // heads
constexpr int CDK = 32;    // head dim
constexpr float C_EPS = 1e-6f;
constexpr float C_INV_TEMP = 0.17677669529663687f;   // 1/sqrt(32)

// Scratch (allocation-free rule: __device__ globals)
__device__ float g_pv[CB * CL * CD];
__device__ float g_dotqk[CB * CH * CL];
__device__ float g_outhead[CB * CL * CD];

extern __shared__ float sm_dyn[];

// ---------------------------------------------------------------------------
// K1: projection kernel.  grid=(8,8,2), block=512, dynamic smem 136KB.
// __launch_bounds__(512, 1): smem caps us at 1 block/SM anyway; tell ptxas
// so it uses the full 128-reg budget instead of starving the pipeline at 37.
//  z=0: fused Q&K projection for head bx, rows [m0,m0+32): pq,pk tiles in
//       registers (2r x 2c microtile, split-K x2), LN fused on q; writes
//       ONLY dot_qk[b,h,j].
//  z=1: V projection 32x32 tile -> g_pv (same micro-structure).
// ---------------------------------------------------------------------------
__global__ __launch_bounds__(512, 1)
void ct_proj_kernel(const float* __restrict__ qin,
                    const float* __restrict__ kin,
                    const float* __restrict__ vin,
                    const float* __restrict__ Wq,
                    const float* __restrict__ Wk,
                    const float* __restrict__ Wv,
                    const float* __restrict__ ln_g,
                    const float* __restrict__ ln_b) {
    const int bz = blockIdx.z;
    int tid = threadIdx.x;
    int m0 = blockIdx.y * 32;
    int n0 = blockIdx.x * 32;          // z=0: head*32 within H*DK; z=1: col tile

    float4* Aq4 = (float4*)sm_dyn;             // [kk(64)][row(32)]
    float4* Ak4 = (float4*)(sm_dyn + 8192);
    float*  Bq  = sm_dyn + 16384;              // [k(256)][col(32)]
    float*  Bk  = sm_dyn + 24576;
    float*  red = sm_dyn + 32768;              // [8][256]

    // microtile coords
    int g   = tid >> 8;                 // split-K half
    int idx = tid & 255;
    int rg  = idx >> 4;                 // row group 0..15 -> rows 2rg,2rg+1
    int cpp = idx & 15;                 // col pair 0..15 -> cols 2cpp,2cpp+1
    int r0 = rg * 2, r1 = r0 + 1, c0 = cpp * 2;
    int kbase = g * 32;                 // kk4 range per half

    if (bz == 0) {
        // ---- issue all async copies (q,k,Wq,Wk) ------------------------
        {
            int r = tid & 31, k4b = tid >> 5;       // k4b 0..15
#pragma unroll
            for (int it = 0; it < 4; it++) {
                int kk = k4b + it * 16;             // 0..63
                __pipeline_memcpy_async(&Aq4[kk * 32 + r], &qin[(m0 + r) * CD + kk * 4], 16);
                __pipeline_memcpy_async(&Ak4[kk * 32 + r], &kin[(m0 + r) * CD + kk * 4], 16);
            }
            int c4 = tid & 7, kb = tid >> 3;        // kb 0..63
#pragma unroll
            for (int it = 0; it < 4; it++) {
                int k = kb + it * 64;               // 0..255
                __pipeline_memcpy_async(&Bq[k * 32 + c4 * 4], &Wq[k * CD + n0 + c4 * 4], 16);
                __pipeline_memcpy_async(&Bk[k * 32 + c4 * 4], &Wk[k * CD + n0 + c4 * 4], 16);
            }
        }
        __pipeline_commit();

        // ---- LN stats from global while copies fly (warp w: rows w,w+16)
        int w = tid >> 5, lane = tid & 31;
        float mu_a, rs_a, mu_b, rs_b;
#pragma unroll
        for (int half = 0; half < 2; half++) {
            int rr = w + half * 16;
            const float* rowp = qin + (m0 + rr) * CD;
            float s1 = 0.f, s2 = 0.f;
#pragma unroll
            for (int e = 0; e < 8; e++) {
                float x = rowp[lane + 32 * e];
                s1 += x; s2 += x * x;
            }
#pragma unroll
            for (int o = 16; o > 0; o >>= 1) {
                s1 += __shfl_xor_sync(0xFFFFFFFFu, s1, o);
                s2 += __shfl_xor_sync(0xFFFFFFFFu, s2, o);
            }
            float mu  = s1 * (1.0f / 256.0f);
            float var = s2 * (1.0f / 256.0f) - mu * mu;
            float rs  = rsqrtf(var + C_EPS);
            if (half == 0) { mu_a = mu; rs_a = rs; }
            else           { mu_b = mu; rs_b = rs; }
        }

        __pipeline_wait_prior(0);
        __syncthreads();

        // ---- in-smem LN transform of Aq (warp w owns rows w, w+16) -----
#pragma unroll
        for (int half = 0; half < 2; half++) {
            int rr = w + half * 16;
            float mu = half ? mu_b : mu_a;
            float rs = half ? rs_b : rs_a;
#pragma unroll
            for (int c = 0; c < 2; c++) {
                int kk = lane + c * 32;
                float4 p  = Aq4[kk * 32 + rr];
                float4 g4 = ((const float4*)ln_g)[kk];
                float4 b4 = ((const float4*)ln_b)[kk];
                p.x = (p.x - mu) * rs * g4.x + b4.x;
                p.y = (p.y - mu) * rs * g4.y + b4.y;
                p.z = (p.z - mu) * rs * g4.z + b4.z;
                p.w = (p.w - mu) * rs * g4.w + b4.w;
                Aq4[kk * 32 + rr] = p;
            }
        }
        __syncthreads();

        // ---- compute: 2r x 2c for both q and k over this K-half --------
        float q00 = 0.f, q01 = 0.f, q10 = 0.f, q11 = 0.f;
        float k00 = 0.f, k01 = 0.f, k10 = 0.f, k11 = 0.f;
#pragma unroll 8
        for (int kk = 0; kk < 32; kk++) {
            int kk4 = kbase + kk;
            float4 aq_0 = Aq4[kk4 * 32 + r0];
            float4 aq_1 = Aq4[kk4 * 32 + r1];
            float4 ak_0 = Ak4[kk4 * 32 + r0];
            float4 ak_1 = Ak4[kk4 * 32 + r1];
            const float* bq = &Bq[(kk4 * 4) * 32 + c0];
            const float* bk = &Bk[(kk4 * 4) * 32 + c0];
            float2 bq0 = *(const float2*)&bq[0 * 32];
            float2 bq1 = *(const float2*)&bq[1 * 32];
            float2 bq2 = *(const float2*)&bq[2 * 32];
            float2 bq3 = *(const float2*)&bq[3 * 32];
            q00 += aq_0.x * bq0.x; q01 += aq_0.x * bq0.y;
            q10 += aq_1.x * bq0.x; q11 += aq_1.x * bq0.y;
            q00 += aq_0.y * bq1.x; q01 += aq_0.y * bq1.y;
            q10 += aq_1.y * bq1.x; q11 += aq_1.y * bq1.y;
            q00 += aq_0.z * bq2.x; q01 += aq_0.z * bq2.y;
            q10 += aq_1.z * bq2.x; q11 += aq_1.z * bq2.y;
            q00 += aq_0.w * bq3.x; q01 += aq_0.w * bq3.y;
            q10 += aq_1.w * bq3.x; q11 += aq_1.w * bq3.y;
            float2 bk0 = *(const float2*)&bk[0 * 32];
            float2 bk1 = *(const float2*)&bk[1 * 32];
            float2 bk2 = *(const float2*)&bk[2 * 32];
            float2 bk3 = *(const float2*)&bk[3 * 32];
            k00 += ak_0.x * bk0.x; k01 += ak_0.x * bk0.y;
            k10 += ak_1.x * bk0.x; k11 += ak_1.x * bk0.y;
            k00 += ak_0.y * bk1.x; k01 += ak_0.y * bk1.y;
            k10 += ak_1.y * bk1.x; k11 += ak_1.y * bk1.y;
            k00 += ak_0.z * bk2.x; k01 += ak_0.z * bk2.y;
            k10 += ak_1.z * bk2.x; k11 += ak_1.z * bk2.y;
            k00 += ak_0.w * bk3.x; k01 += ak_0.w * bk3.y;
            k10 += ak_1.w * bk3.x; k11 += ak_1.w * bk3.y;
        }

        // ---- combine split-K halves ------------------------------------
        if (g == 1) {
            red[0 * 256 + idx] = q00; red[1 * 256 + idx] = q01;
            red[2 * 256 + idx] = q10; red[3 * 256 + idx] = q11;
            red[4 * 256 + idx] = k00; red[5 * 256 + idx] = k01;
            red[6 * 256 + idx] = k10; red[7 * 256 + idx] = k11;
        }
        __syncthreads();
        if (g == 0) {
            q00 += red[0 * 256 + idx]; q01 += red[1 * 256 + idx];
            q10 += red[2 * 256 + idx]; q11 += red[3 * 256 + idx];
            k00 += red[4 * 256 + idx]; k01 += red[5 * 256 + idx];
            k10 += red[6 * 256 + idx]; k11 += red[7 * 256 + idx];

            // ---- dot over the 32-col head dim (16-lane butterfly) ------
            float d0 = q00 * k00 + q01 * k01;
            float d1 = q10 * k10 + q11 * k11;
#pragma unroll
            for (int o = 1; o < 16; o <<= 1) {
                d0 += __shfl_xor_sync(0xFFFFFFFFu, d0, o);
                d1 += __shfl_xor_sync(0xFFFFFFFFu, d1, o);
            }
            if (cpp == 0) {
                int m = m0 + r0;
                g_dotqk[(m >> 7) * (CH * CL) + blockIdx.x * CL + (m & 127)] = d0;
                m = m0 + r1;
                g_dotqk[(m >> 7) * (CH * CL) + blockIdx.x * CL + (m & 127)] = d1;
            }
        }
    } else {
        // ---- V projection: 32x32 tile, 2r x 2c, split-K x2 -------------
        {
            int r = tid & 31, k4b = tid >> 5;
#pragma unroll
            for (int it = 0; it < 4; it++) {
                int kk = k4b + it * 16;
                __pipeline_memcpy_async(&Aq4[kk * 32 + r], &vin[(m0 + r) * CD + kk * 4], 16);
            }
            int c4 = tid & 7, kb = tid >> 3;
#pragma unroll
            for (int it = 0; it < 4; it++) {
                int k = kb + it * 64;
                __pipeline_memcpy_async(&Bq[k * 32 + c4 * 4], &Wv[k * CD + n0 + c4 * 4], 16);
            }
        }
        __pipeline_commit();
        __pipeline_wait_prior(0);
        __syncthreads();

        float v00 = 0.f, v01 = 0.f, v10 = 0.f, v11 = 0.f;
#pragma unroll 8
        for (int kk = 0; kk < 32; kk++) {
            int kk4 = kbase + kk;
            float4 a_0 = Aq4[kk4 * 32 + r0];
            float4 a_1 = Aq4[kk4 * 32 + r1];
            const float* bv = &Bq[(kk4 * 4) * 32 + c0];
            float2 b0 = *(const float2*)&bv[0 * 32];
            float2 b1 = *(const float2*)&bv[1 * 32];
            float2 b2 = *(const float2*)&bv[2 * 32];
            float2 b3 = *(const float2*)&bv[3 * 32];
            v00 += a_0.x * b0.x; v01 += a_0.x * b0.y;
            v10 += a_1.x * b0.x; v11 += a_1.x * b0.y;
            v00 += a_0.y * b1.x; v01 += a_0.y * b1.y;
            v10 += a_1.y * b1.x; v11 += a_1.y * b1.y;
            v00 += a_0.z * b2.x; v01 += a_0.z * b2.y;
            v10 += a_1.z * b2.x; v11 += a_1.z * b2.y;
            v00 += a_0.w * b3.x; v01 += a_0.w * b3.y;
            v10 += a_1.w * b3.x; v11 += a_1.w * b3.y;
        }

        if (g == 1) {
            red[0 * 256 + idx] = v00; red[1 * 256 + idx] = v01;
            red[2 * 256 + idx] = v10; red[3 * 256 + idx] = v11;
        }
        __syncthreads();
        if (g == 0) {
            v00 += red[0 * 256 + idx]; v01 += red[1 * 256 + idx];
            v10 += red[2 * 256 + idx]; v11 += red[3 * 256 + idx];
            *(float2*)&g_pv[(m0 + r0) * CD + n0 + c0] = make_float2(v00, v01);
            *(float2*)&g_pv[(m0 + r1) * CD + n0 + c0] = make_float2(v10, v11);
        }
    }
}

// ---------------------------------------------------------------------------
// K2: fused attention per (b,i).  Prologue computes time-kernel tables
// (chi, lb) in smem; warp h owns head h: shuffle-only softmax, attn write,
// V-reduction.  grid=256 (b*128+i), block=256, static smem.
// ---------------------------------------------------------------------------
__global__ __launch_bounds__(256)
void ct_attn_kernel(const float* __restrict__ t,
                    const float* __restrict__ omega,
                    const float* __restrict__ s,
                    float* __restrict__ attn_out) {
    int bid = blockIdx.x;
    int b = bid >> 7;
    int i = bid & 127;
    int tid = threadIdx.x;
    int h = tid >> 5;
    int lane = tid & 31;
    int j0 = lane * 4;

    __shared__ float sh_lb[128];        // omega * INV_TEMP * psi
    __shared__ float sh_chi[128];       // sum_r exp(-dt*s_r)
    __shared__ float sh_ws[8][128];

    if (tid < 128) {
        int j = tid;
        float s0 = s[0], s1 = s[1], s2 = s[2], s3 = s[3];
        float dt = fabsf(t[b * CL + i] - t[b * CL + j]);
        float c0 = __expf(-dt * s0), c1 = __expf(-dt * s1);
        float c2 = __expf(-dt * s2), c3 = __expf(-dt * s3);
        sh_chi[j] = (c0 + c1) + (c2 + c3);
        float psi = (c0 * c0 + c1 * c1) + (c2 * c2 + c3 * c3);
        sh_lb[j] = omega[(b * CL + i) * CL + j] * C_INV_TEMP * psi;
    }
    __syncthreads();

    float4 dq = *(const float4*)&g_dotqk[b * (CH * CL) + h * CL + j0];
    float4 lb = *(const float4*)&sh_lb[j0];
    float4 ch = *(const float4*)&sh_chi[j0];

    float l0 = (j0 + 0 <= i) ? lb.x * dq.x : -1e9f;
    float l1 = (j0 + 1 <= i) ? lb.y * dq.y : -1e9f;
    float l2 = (j0 + 2 <= i) ? lb.z * dq.z : -1e9f;
    float l3 = (j0 + 3 <= i) ? lb.w * dq.w : -1e9f;

    float m = fmaxf(fmaxf(l0, l1), fmaxf(l2, l3));
#pragma unroll
    for (int o = 16; o > 0; o >>= 1)
        m = fmaxf(m, __shfl_xor_sync(0xFFFFFFFFu, m, o));

    float e0 = __expf(l0 - m), e1 = __expf(l1 - m);
    float e2 = __expf(l2 - m), e3 = __expf(l3 - m);
    float su = (e0 + e1) + (e2 + e3);
#pragma unroll
    for (int o = 16; o > 0; o >>= 1)
        su += __shfl_xor_sync(0xFFFFFFFFu, su, o);

    float inv = 1.0f / su;
    float4 a4 = make_float4(e0 * inv, e1 * inv, e2 * inv, e3 * inv);
    *(float4*)&attn_out[((b * CH + h) * CL + i) * CL + j0] = a4;

    float4 w4 = make_float4(a4.x * ch.x, a4.y * ch.y, a4.z * ch.z, a4.w * ch.w);
    *(float4*)&sh_ws[h][j0] = w4;
    __syncwarp();

    // V reduction: outhead[b,i,h,d] = sum_j ws[h][j] * pv[b,j,h,d]
    const float* pvp = g_pv + b * CL * CD + h * CDK + lane;
    const float* wsp = sh_ws[h];
    float a0 = 0.f, a1 = 0.f, a2 = 0.f, a3 = 0.f;
#pragma unroll 8
    for (int j = 0; j < 128; j += 4) {
        a0 += wsp[j + 0] * pvp[(j + 0) * CD];
        a1 += wsp[j + 1] * pvp[(j + 1) * CD];
        a2 += wsp[j + 2] * pvp[(j + 2) * CD];
        a3 += wsp[j + 3] * pvp[(j + 3) * CD];
    }
    g_outhead[bid * CD + h * CDK + lane] = (a0 + a1) + (a2 + a3);
}

// ---------------------------------------------------------------------------
// K3: out = outhead @ fc_w + fc_b + q (residual).
// grid=(8,16), block=512: split-K x2 (each half does K=128), smem combine.
// __launch_bounds__(512, 1): unlock the register budget (see K1 comment).
// ---------------------------------------------------------------------------
__global__ __launch_bounds__(512, 1)
void ct_final_kernel(const float* __restrict__ W,
                     const float* __restrict__ bias,
                     const float* __restrict__ resid,
                     float* __restrict__ out) {
    float4* A4  = (float4*)sm_dyn;
    float*  Bs  = sm_dyn + 4096;
    float*  red = sm_dyn + 4096 + 8192;

    int tid = threadIdx.x;
    int m0 = blockIdx.y * 16, n0 = blockIdx.x * 32;

    {
        int r = tid & 15, kk4g = tid >> 4;       // 0..31
#pragma unroll
        for (int it = 0; it < 2; it++) {
            int kk = kk4g + it * 32;
            __pipeline_memcpy_async(&A4[kk * 16 + r],
                                    &g_outhead[(m0 + r) * CD + kk * 4], 16);
        }
        int c4 = tid & 7, k0 = tid >> 3;         // 0..63
#pragma unroll
        for (int it = 0; it < 4; it++) {
            int kx = k0 + it * 64;
            __pipeline_memcpy_async(&Bs[kx * 32 + c4 * 4],
                                    &W[kx * CD + n0 + c4 * 4], 16);
        }
    }
    __pipeline_commit();
    __pipeline_wait_prior(0);
    __syncthreads();

    int g   = tid >> 8;                  // split-K half
    int idx = tid & 255;
    int lr  = idx >> 4;
    int lc2 = (idx & 15) * 2;
    float acc0 = 0.f, acc1 = 0.f;
    int base = g * 32;

#pragma unroll 16
    for (int kk = 0; kk < 32; kk++) {
        int kk4 = base + kk;
        float4 a4 = A4[kk4 * 16 + lr];
        const float* brow = &Bs[(kk4 * 4) * 32 + lc2];
        float2 b0 = *(const float2*)&brow[0 * 32];
        float2 b1 = *(const float2*)&brow[1 * 32];
        float2 b2 = *(const float2*)&brow[2 * 32];
        float2 b3 = *(const float2*)&brow[3 * 32];
        acc0 += a4.x * b0.x; acc1 += a4.x * b0.y;
        acc0 += a4.y * b1.x; acc1 += a4.y * b1.y;
        acc0 += a4.z * b2.x; acc1 += a4.z * b2.y;
        acc0 += a4.w * b3.x; acc1 += a4.w * b3.y;
    }

    if (g == 1) {
        red[idx * 2 + 0] = acc0;
        red[idx * 2 + 1] = acc1;
    }
    __syncthreads();
    if (g == 0) {
        acc0 += red[idx * 2 + 0];
        acc1 += red[idx * 2 + 1];
        int row = m0 + lr, col = n0 + lc2;
        float2 bi = *(const float2*)&bias[col];
        float2 re = *(const float2*)&resid[row * CD + col];
        *(float2*)&out[row * CD + col] =
            make_float2(acc0 + bi.x + re.x, acc1 + bi.y + re.y);
    }
}

// ---------------------------------------------------------------------------
// Launch.  Inputs: q,k,v,t,omega,mask,Wq,Wk,Wv,s,fc_w,fc_b,ln_g,ln_b
// Output: out (65536 f32) then attn (262144 f32)
// ---------------------------------------------------------------------------
extern "C" void kernel_launch(void* const* d_in, const int* in_sizes, int n_in,
                              void* d_out, int out_size) {
    const float* q     = (const float*)d_in[0];
    const float* k     = (const float*)d_in[1];
    const float* v     = (const float*)d_in[2];
    const float* t     = (const float*)d_in[3];
    const float* omega = (const float*)d_in[4];
    // d_in[5] = mask (causal triu) -- applied analytically
    const float* Wq    = (const float*)d_in[6];
    const float* Wk    = (const float*)d_in[7];
    const float* Wv    = (const float*)d_in[8];
    const float* s     = (const float*)d_in[9];
    const float* fc_w  = (const float*)d_in[10];
    const float* fc_b  = (const float*)d_in[11];
    const float* ln_g  = (const float*)d_in[12];
    const float* ln_b  = (const float*)d_in[13];

    float* out      = (float*)d_out;
    float* attn_out = out + CB * CL * CD;

    // Opt in to >48KB dynamic smem (capture-safe host calls)
    cudaFuncSetAttribute(ct_proj_kernel,
                         cudaFuncAttributeMaxDynamicSharedMemorySize, 140 * 1024);
    cudaFuncSetAttribute(ct_final_kernel,
                         cudaFuncAttributeMaxDynamicSharedMemorySize, 50 * 1024);

    ct_proj_kernel<<<dim3(8, 8, 2), 512, 140 * 1024>>>(q, k, v, Wq, Wk, Wv, ln_g, ln_b);
    ct_attn_kernel<<<CB * CL, 256>>>(t, omega, s, attn_out);
    ct_final_kernel<<<dim3(8, 16), 512, 50 * 1024>>>(fc_w, fc_b, q, out);
}